// round 9
// baseline (speedup 1.0000x reference)
#include <cuda_runtime.h>
#include <cuda_bf16.h>
#include <cstdint>
#include <math.h>

#define EPS_BN 1e-5f

// ===========================================================================
// scratch (device globals)
// ===========================================================================
__device__ float    g_seq [8388608];      // rows-LSTM input NHWC fp32
__device__ float    g_xg  [33554432];     // 32768 x 1024
__device__ float    g_rows[8388608];      // rows-LSTM out [b][w][h][c] fp32
__device__ uint32_t g_cols_hl[8388608];   // cols-LSTM out NHWC (hi,lo) bf16x2
__device__ uint32_t g_hlB[8388608];       // conv temps, NHWC hl
__device__ uint32_t g_hlC[8388608];
__device__ uint32_t g_hlD[4194304];       // 128-channel temp
__device__ __nv_bfloat16 g_wb[11206656];  // conv weights: [ot][tap][cc][pass][k64][n128]
__device__ uint2    g_whh_frag[131072];   // recurrence B-fragments [dir][pass][kt16][ntg64][lane32]
__device__ float    g_bias2[2][512];

// wb region offsets (elements)
#define WB_A 0u
#define WB_B 2359296u
#define WB_C 4718592u
#define WB_E 9437184u
#define WB_F 10616832u

// ===========================================================================
// mma.sync / ldmatrix helpers (legacy HMMA path — legal on compute_103)
// ===========================================================================
__device__ __forceinline__ uint32_t smem_u32(const void* p) {
    uint32_t a;
    asm("{ .reg .u64 t; cvta.to.shared.u64 t, %1; cvt.u32.u64 %0, t; }" : "=r"(a) : "l"(p));
    return a;
}
__device__ __forceinline__ void ldsm4(uint32_t* r, uint32_t addr) {
    asm volatile("ldmatrix.sync.aligned.m8n8.x4.shared.b16 {%0,%1,%2,%3}, [%4];"
        : "=r"(r[0]), "=r"(r[1]), "=r"(r[2]), "=r"(r[3]) : "r"(addr));
}
__device__ __forceinline__ void ldsm4t(uint32_t* r, uint32_t addr) {
    asm volatile("ldmatrix.sync.aligned.m8n8.x4.trans.shared.b16 {%0,%1,%2,%3}, [%4];"
        : "=r"(r[0]), "=r"(r[1]), "=r"(r[2]), "=r"(r[3]) : "r"(addr));
}
__device__ __forceinline__ void mma16816(float* c, const uint32_t* a, uint32_t b0, uint32_t b1) {
    asm volatile("mma.sync.aligned.m16n8k16.row.col.f32.bf16.bf16.f32 "
        "{%0,%1,%2,%3}, {%4,%5,%6,%7}, {%8,%9}, {%0,%1,%2,%3};"
        : "+f"(c[0]), "+f"(c[1]), "+f"(c[2]), "+f"(c[3])
        : "r"(a[0]), "r"(a[1]), "r"(a[2]), "r"(a[3]), "r"(b0), "r"(b1));
}
__device__ __forceinline__ uint32_t hl_pack(float v) {
    __nv_bfloat16 hi = __float2bfloat16(v);
    __nv_bfloat16 lo = __float2bfloat16(v - __bfloat162float(hi));
    return (uint32_t)__bfloat16_as_ushort(hi) | ((uint32_t)__bfloat16_as_ushort(lo) << 16);
}
__device__ __forceinline__ uint32_t dup_hi(float w) {
    uint32_t h = (uint32_t)__bfloat16_as_ushort(__float2bfloat16(w));
    return h | (h << 16);
}
__device__ __forceinline__ uint32_t lo_only(float w) {
    __nv_bfloat16 hi = __float2bfloat16(w);
    return (uint32_t)__bfloat16_as_ushort(__float2bfloat16(w - __bfloat162float(hi)));
}

// ===========================================================================
// prep: bias sums, conv weight tiles, recurrence B-fragments
// ===========================================================================
__global__ void prep_kernel(const float* __restrict__ whh_f, const float* __restrict__ whh_b,
                            const float* __restrict__ bih_f, const float* __restrict__ bhh_f,
                            const float* __restrict__ bih_b, const float* __restrict__ bhh_b,
                            const float* __restrict__ c2w1, const float* __restrict__ c2w2,
                            const float* __restrict__ cvw1, const float* __restrict__ cvw2)
{
    unsigned i = blockIdx.x * 256u + threadIdx.x;
    if (i < 512u) {
        g_bias2[0][i] = bih_f[i] + bhh_f[i];
        g_bias2[1][i] = bih_b[i] + bhh_b[i];
    }
    // recurrence B-fragments: i = dir*65536 + pass*32768 + kt*2048 + ntg*32 + lane
    if (i < 131072u) {
        int lane = i & 31;
        int ntg  = (i >> 5) & 63;
        int kt   = (i >> 11) & 15;
        int pass = (i >> 15) & 1;
        int dir  = (int)(i >> 16);
        const float* whh = dir ? whh_b : whh_f;
        int n  = ntg * 8 + (lane >> 2);
        int c0 = kt * 8 + (lane & 3);
        int c1 = c0 + 4;
        float w0 = whh[n * 128 + c0];
        float w1 = whh[n * 128 + c1];
        uint2 v;
        if (pass == 0) { v.x = dup_hi(w0);  v.y = dup_hi(w1); }
        else           { v.x = lo_only(w0); v.y = lo_only(w1); }
        g_whh_frag[i] = v;
    }
    if (i < 11206656u) {
        unsigned l; int CC; int kind;
        if      (i < WB_B) { l = i - WB_A; CC = 8;  kind = 0; }
        else if (i < WB_C) { l = i - WB_B; CC = 8;  kind = 1; }
        else if (i < WB_E) { l = i - WB_C; CC = 16; kind = 2; }
        else if (i < WB_F) { l = i - WB_E; CC = 8;  kind = 3; }
        else               { l = i - WB_F; CC = 4;  kind = 4; }
        int n    = l & 127;
        int k    = (l >> 7) & 63;
        int pass = (l >> 13) & 1;
        unsigned q = l >> 14;
        int cc  = q % CC;  q /= CC;
        int tap = q % 9;   q /= 9;
        int ot  = q;
        int c  = cc * 32 + (k >> 1);
        int oc = ot * 128 + n;
        int odd = k & 1;
        float w;
        if      (kind == 0) w = c2w1[((size_t)oc * 512 + c) * 9 + tap]
                              + c2w1[((size_t)oc * 512 + c + 256) * 9 + tap];
        else if (kind == 1) w = c2w2[((size_t)oc * 256 + c) * 9 + tap];
        else if (kind == 2) w = c2w1[((size_t)oc * 512 + c) * 9 + tap];
        else if (kind == 3) w = cvw1[((size_t)oc * 256 + c) * 9 + tap];
        else                w = cvw2[((size_t)oc * 128 + c) * 9 + tap];
        __nv_bfloat16 hi = __float2bfloat16(w);
        __nv_bfloat16 val;
        if (pass == 0) val = hi;
        else val = odd ? __float2bfloat16(0.f)
                       : __float2bfloat16(w - __bfloat162float(hi));
        g_wb[i] = val;
    }
}

// ===========================================================================
// build rows-sequence (upsample + concat, NHWC fp32)
// ===========================================================================
__global__ __launch_bounds__(256) void build_seq_kernel(const float* __restrict__ x2,
                                                        const float* __restrict__ x1)
{
    __shared__ float sh[32][65];
    int bh = blockIdx.x;
    int b = bh >> 6, h = bh & 63;
    int ct = blockIdx.y;
    int c0 = ct * 32;
    int tid = threadIdx.x;

    if (ct < 4) {
        for (int idx = tid; idx < 32 * 64; idx += 256) {
            int ci = idx >> 6, w = idx & 63;
            sh[ci][w] = x2[(((size_t)b * 128 + (c0 + ci)) * 64 + h) * 64 + w];
        }
    } else {
        int cc0 = c0 - 128;
        float py = (float)h * 31.0f / 63.0f;
        int yl = (int)floorf(py);
        float wy = py - (float)yl;
        int yh = min(yl + 1, 31);
        for (int idx = tid; idx < 32 * 64; idx += 256) {
            int ci = idx >> 6, w = idx & 63;
            float px = (float)w * 31.0f / 63.0f;
            int xl = (int)floorf(px);
            float wx = px - (float)xl;
            int xh = min(xl + 1, 31);
            const float* base = x1 + ((size_t)b * 128 + (cc0 + ci)) * 1024;
            float v00 = base[yl * 32 + xl], v01 = base[yl * 32 + xh];
            float v10 = base[yh * 32 + xl], v11 = base[yh * 32 + xh];
            float v0 = v00 * (1.f - wx) + v01 * wx;
            float v1 = v10 * (1.f - wx) + v11 * wx;
            sh[ci][w] = v0 * (1.f - wy) + v1 * wy;
        }
    }
    __syncthreads();
    for (int idx = tid; idx < 32 * 64; idx += 256) {
        int w = idx >> 5, cl = idx & 31;
        g_seq[((size_t)bh * 64 + w) * 256 + c0 + cl] = sh[cl][w];
    }
}

// ===========================================================================
// GEMM: xg[32768,1024] = A[32768,256] @ [Wih_f;Wih_b]^T + bias  (scalar fp32)
// ===========================================================================
__global__ __launch_bounds__(256) void gemm_xg_kernel(int mode,
                                                      const float* __restrict__ wih_f,
                                                      const float* __restrict__ wih_b)
{
    const float* A = mode ? g_rows : g_seq;
    int mbase = blockIdx.x * 128;
    int nbase = blockIdx.y * 64;
    const float* Wg;
    const float* bias;
    int nloc;
    if (nbase < 512) { Wg = wih_f; bias = g_bias2[0]; nloc = nbase; }
    else             { Wg = wih_b; bias = g_bias2[1]; nloc = nbase - 512; }

    __shared__ __align__(16) float a_sh[16][132];
    __shared__ __align__(16) float b_sh[16][68];

    int tid = threadIdx.x;
    int tm = tid >> 4;
    int tn = tid & 15;
    int lma = tid >> 1;
    int lka = (tid & 1) * 8;
    int lmb = tid >> 2;
    int lkb = (tid & 3) * 4;

    float acc[8][4];
#pragma unroll
    for (int i = 0; i < 8; i++)
#pragma unroll
        for (int j = 0; j < 4; j++) acc[i][j] = 0.f;

    for (int k0 = 0; k0 < 256; k0 += 16) {
        float4 va0 = *(const float4*)&A [((size_t)(mbase + lma)) * 256 + k0 + lka];
        float4 va1 = *(const float4*)&A [((size_t)(mbase + lma)) * 256 + k0 + lka + 4];
        float4 vb  = *(const float4*)&Wg[((size_t)(nloc + lmb)) * 256 + k0 + lkb];
        a_sh[lka + 0][lma] = va0.x; a_sh[lka + 1][lma] = va0.y;
        a_sh[lka + 2][lma] = va0.z; a_sh[lka + 3][lma] = va0.w;
        a_sh[lka + 4][lma] = va1.x; a_sh[lka + 5][lma] = va1.y;
        a_sh[lka + 6][lma] = va1.z; a_sh[lka + 7][lma] = va1.w;
        b_sh[lkb + 0][lmb] = vb.x;  b_sh[lkb + 1][lmb] = vb.y;
        b_sh[lkb + 2][lmb] = vb.z;  b_sh[lkb + 3][lmb] = vb.w;
        __syncthreads();
#pragma unroll
        for (int k = 0; k < 16; k++) {
            float4 a0 = *(const float4*)&a_sh[k][tm * 8];
            float4 a1 = *(const float4*)&a_sh[k][tm * 8 + 4];
            float4 b4 = *(const float4*)&b_sh[k][tn * 4];
            float av[8] = {a0.x, a0.y, a0.z, a0.w, a1.x, a1.y, a1.z, a1.w};
            float bv[4] = {b4.x, b4.y, b4.z, b4.w};
#pragma unroll
            for (int i = 0; i < 8; i++)
#pragma unroll
                for (int j = 0; j < 4; j++) acc[i][j] += av[i] * bv[j];
        }
        __syncthreads();
    }
    float4 bb = *(const float4*)&bias[nloc + tn * 4];
    float bv[4] = {bb.x, bb.y, bb.z, bb.w};
#pragma unroll
    for (int i = 0; i < 8; i++) {
        float* dst = &g_xg[(size_t)(mbase + tm * 8 + i) * 1024 + nbase + tn * 4];
        *(float4*)dst = make_float4(acc[i][0] + bv[0], acc[i][1] + bv[1],
                                    acc[i][2] + bv[2], acc[i][3] + bv[3]);
    }
}

// ===========================================================================
// LSTM recurrence via tensor cores.
// 64 blocks = 2 dirs x 32; 16 seqs/block; 256 threads = 8 warps.
// Per step: gates[16,512] = mma(h_hl[16,256] x whh_frag) (+xg in activation).
// h stored hl-packed in smem; B fragments streamed straight from L2.
// ===========================================================================
__global__ __launch_bounds__(256) void lstm_kernel(int mode)
{
    int dir = blockIdx.x >> 5;
    int blk = blockIdx.x & 31;
    int base_n = blk * 16;
    const float* xg = g_xg + dir * 512;
    const uint2* frag = g_whh_frag + dir * 65536;

    __shared__ __align__(16) uint32_t a_sh[16][132];   // h hl-packed [seq][cell]
    __shared__ __align__(16) float g_sh[16][516];      // gates from mma

    int tid = threadIdx.x, lane = tid & 31, wid = tid >> 5;
    int ntg_base = wid * 8;

    // h = 0
    for (int idx = tid; idx < 16 * 132; idx += 256) ((uint32_t*)a_sh)[idx] = 0u;
    __syncthreads();

    uint32_t a_base = smem_u32(a_sh);
    uint32_t a_addr = a_base + ((lane & 7) + ((lane >> 3) & 1) * 8) * 528 + (lane >> 4) * 16;

    float c_reg[8];
#pragma unroll
    for (int p = 0; p < 8; p++) c_reg[p] = 0.f;

    int r0 = lane >> 2;
    int ncol = (lane & 3) * 2;

    for (int t = 0; t < 64; t++) {
        int ta = dir ? (63 - t) : t;
        float acc[8][4];
#pragma unroll
        for (int j = 0; j < 8; j++)
#pragma unroll
            for (int q = 0; q < 4; q++) acc[j][q] = 0.f;

        // ---- recurrent GEMM: 16 k-tiles x 2 hl passes x 8 n-tiles ----
        for (int kt = 0; kt < 16; kt++) {
            uint32_t a[4];
            ldsm4(a, a_addr + kt * 32);
#pragma unroll
            for (int pass = 0; pass < 2; pass++) {
                const uint2* fp = frag + ((size_t)((pass * 16 + kt) * 64 + ntg_base)) * 32 + lane;
#pragma unroll
                for (int j = 0; j < 8; j++) {
                    uint2 bv = fp[j * 32];
                    mma16816(acc[j], a, bv.x, bv.y);
                }
            }
        }

        // ---- store gate fragments to smem ----
#pragma unroll
        for (int j = 0; j < 8; j++) {
            int n = (ntg_base + j) * 8 + ncol;
            *(float2*)&g_sh[r0][n]     = make_float2(acc[j][0], acc[j][1]);
            *(float2*)&g_sh[r0 + 8][n] = make_float2(acc[j][2], acc[j][3]);
        }
        __syncthreads();

        // ---- activation: 8 cells per thread, fold in xg ----
#pragma unroll
        for (int p = 0; p < 8; p++) {
            int e = tid + p * 256;
            int s = e >> 7, j = e & 127;
            int n = base_n + s;
            size_t xr = ((size_t)n * 64 + ta) * 1024;
            float iv = g_sh[s][j]       + xg[xr + j];
            float fv = g_sh[s][128 + j] + xg[xr + 128 + j];
            float gv = g_sh[s][256 + j] + xg[xr + 256 + j];
            float ov = g_sh[s][384 + j] + xg[xr + 384 + j];
            float ig = 1.f / (1.f + expf(-iv));
            float fg = 1.f / (1.f + expf(-fv));
            float og = 1.f / (1.f + expf(-ov));
            c_reg[p] = fg * c_reg[p] + ig * tanhf(gv);
            float h = og * tanhf(c_reg[p]);
            a_sh[s][j] = hl_pack(h);
            int b = n >> 6, loc = n & 63;
            if (mode == 0) {
                g_rows[(((size_t)(b * 64 + ta)) * 64 + loc) * 256 + dir * 128 + j] = h;
            } else {
                g_cols_hl[(((size_t)(b * 64 + ta)) * 64 + loc) * 256 + dir * 128 + j] = hl_pack(h);
            }
        }
        __syncthreads();
    }
}

// ===========================================================================
// mma.sync bf16 implicit-GEMM 3x3 conv (unchanged from R8).
// ===========================================================================
#define CONV_A_BYTES   (128 * 144)
#define CONV_B_BYTES   (64 * 272)
#define CONV_SMEM      (CONV_A_BYTES + 2 * CONV_B_BYTES)

__global__ __launch_bounds__(256, 2) void conv_mma_kernel(
    const uint32_t* __restrict__ in0, int C0,
    const uint32_t* __restrict__ in1, int C1,
    unsigned wb_off,
    const float* __restrict__ gamma, const float* __restrict__ beta,
    void* outp, int OC, int final_nchw)
{
    extern __shared__ __align__(16) char smem[];
    char* a_sh = smem;
    char* b_sh = smem + CONV_A_BYTES;
    __shared__ float scs[128], bbs[128];

    int tid = threadIdx.x;
    int lane = tid & 31, wid = tid >> 5;
    int warp_m = wid & 3, warp_n = wid >> 2;
    int bx = blockIdx.x;
    int b = bx >> 5, y0 = (bx & 31) * 2;
    int ot = blockIdx.y, ocb = ot * 128;
    int CIN = C0 + C1, CC = CIN >> 5;

    if (tid < 128) {
        scs[tid] = gamma[ocb + tid] * rsqrtf(1.f + EPS_BN);
        bbs[tid] = beta[ocb + tid];
    }

    float acc[2][8][4];
#pragma unroll
    for (int m = 0; m < 2; m++)
#pragma unroll
        for (int j = 0; j < 8; j++)
#pragma unroll
            for (int q = 0; q < 4; q++) acc[m][j][q] = 0.f;

    uint32_t a_base = smem_u32(a_sh);
    uint32_t b_base = smem_u32(b_sh);

    int arow = warp_m * 32 + (lane & 7) + ((lane >> 3) & 1) * 8;
    uint32_t a_addr0 = a_base + arow * 144 + ((lane >> 4) * 16);
    int brow = (lane & 7) + ((lane >> 3) & 1) * 8;
    int bcol = warp_n * 64 + ((lane >> 4) * 8);
    uint32_t b_addr0 = b_base + brow * 272 + bcol * 2;

    int s_px = tid >> 1, s_half = tid & 1;
    int s_yo = s_px >> 6, s_x = s_px & 63;

    for (int tap = 0; tap < 9; tap++) {
        int ty = tap / 3 - 1, tx = tap % 3 - 1;
        int ys = y0 + s_yo + ty;
        int xs = s_x + tx;
        bool ok = ((unsigned)ys < 64u) && ((unsigned)xs < 64u);
        for (int cc = 0; cc < CC; cc++) {
            {
                int c0 = cc * 32 + s_half * 16;
                const uint4* src;
                if (c0 < C0) src = (const uint4*)(in0 + ((size_t)((b * 64 + ys) * 64 + xs)) * C0 + c0);
                else         src = (const uint4*)(in1 + ((size_t)((b * 64 + ys) * 64 + xs)) * C1 + (c0 - C0));
                uint4* dst = (uint4*)(a_sh + s_px * 144 + s_half * 64);
#pragma unroll
                for (int i = 0; i < 4; i++) {
                    uint4 v = make_uint4(0u, 0u, 0u, 0u);
                    if (ok) v = src[i];
                    dst[i] = v;
                }
            }
            const uint4* wsrc = (const uint4*)(g_wb + wb_off +
                ((size_t)((ot * 9 + tap) * CC + cc)) * 16384u);
#pragma unroll
            for (int i = 0; i < 8; i++) {
                int idx = tid + i * 256;
                int pofs = (idx >= 1024) ? CONV_B_BYTES : 0;
                int li = idx & 1023;
                *(uint4*)(b_sh + pofs + (li >> 4) * 272 + (li & 15) * 16) = wsrc[idx];
            }
            __syncthreads();
#pragma unroll
            for (int pass = 0; pass < 2; pass++) {
                uint32_t bp = b_addr0 + pass * CONV_B_BYTES;
#pragma unroll
                for (int ksub = 0; ksub < 4; ksub++) {
                    uint32_t a0[4], a1[4];
                    ldsm4(a0, a_addr0 + ksub * 32);
                    ldsm4(a1, a_addr0 + 16 * 144 + ksub * 32);
                    uint32_t bfr[4][4];
#pragma unroll
                    for (int p = 0; p < 4; p++)
                        ldsm4t(bfr[p], bp + ksub * 16 * 272 + p * 32);
#pragma unroll
                    for (int j = 0; j < 8; j++) {
                        uint32_t bq0 = bfr[j >> 1][(j & 1) * 2];
                        uint32_t bq1 = bfr[j >> 1][(j & 1) * 2 + 1];
                        mma16816(acc[0][j], a0, bq0, bq1);
                        mma16816(acc[1][j], a1, bq0, bq1);
                    }
                }
            }
            __syncthreads();
        }
    }

#pragma unroll
    for (int m = 0; m < 2; m++) {
        int px0 = warp_m * 32 + m * 16 + (lane >> 2);
#pragma unroll
        for (int j = 0; j < 8; j++) {
            int oc = warp_n * 64 + j * 8 + (lane & 3) * 2;
            float sc0 = scs[oc], sc1 = scs[oc + 1];
            float bb0 = bbs[oc], bb1 = bbs[oc + 1];
            float v00 = fmaxf(fmaf(acc[m][j][0], sc0, bb0), 0.f);
            float v01 = fmaxf(fmaf(acc[m][j][1], sc1, bb1), 0.f);
            float v10 = fmaxf(fmaf(acc[m][j][2], sc0, bb0), 0.f);
            float v11 = fmaxf(fmaf(acc[m][j][3], sc1, bb1), 0.f);
            if (!final_nchw) {
                uint32_t* out = (uint32_t*)outp;
                size_t base0 = ((size_t)((b * 64 + (y0 + (px0 >> 6))) * 64 + (px0 & 63))) * OC + ocb + oc;
                int px1 = px0 + 8;
                size_t base1 = ((size_t)((b * 64 + (y0 + (px1 >> 6))) * 64 + (px1 & 63))) * OC + ocb + oc;
                *(uint2*)(out + base0) = make_uint2(hl_pack(v00), hl_pack(v01));
                *(uint2*)(out + base1) = make_uint2(hl_pack(v10), hl_pack(v11));
            } else {
                float* out = (float*)outp;
                size_t r0 = ((size_t)b * OC + ocb + oc) * 4096 + y0 * 64;
                size_t r1 = ((size_t)b * OC + ocb + oc + 1) * 4096 + y0 * 64;
                out[r0 + px0] = v00;
                out[r1 + px0] = v01;
                out[r0 + px0 + 8] = v10;
                out[r1 + px0 + 8] = v11;
            }
        }
    }
}

// ===========================================================================
// launcher
// ===========================================================================
extern "C" void kernel_launch(void* const* d_in, const int* in_sizes, int n_in,
                              void* d_out, int out_size)
{
    const float* x1    = (const float*)d_in[0];
    const float* x2    = (const float*)d_in[1];
    const float* wih_f = (const float*)d_in[2];
    const float* whh_f = (const float*)d_in[3];
    const float* bih_f = (const float*)d_in[4];
    const float* bhh_f = (const float*)d_in[5];
    const float* wih_b = (const float*)d_in[6];
    const float* whh_b = (const float*)d_in[7];
    const float* bih_b = (const float*)d_in[8];
    const float* bhh_b = (const float*)d_in[9];
    const float* c2_w1 = (const float*)d_in[10];
    const float* c2_g1 = (const float*)d_in[11];
    const float* c2_b1 = (const float*)d_in[12];
    const float* c2_w2 = (const float*)d_in[13];
    const float* c2_g2 = (const float*)d_in[14];
    const float* c2_b2 = (const float*)d_in[15];
    const float* cv_w1 = (const float*)d_in[16];
    const float* cv_g1 = (const float*)d_in[17];
    const float* cv_b1 = (const float*)d_in[18];
    const float* cv_w2 = (const float*)d_in[19];
    const float* cv_g2 = (const float*)d_in[20];
    const float* cv_b2 = (const float*)d_in[21];

    uint32_t *p_cols = nullptr, *p_hlB = nullptr, *p_hlC = nullptr, *p_hlD = nullptr;
    cudaGetSymbolAddress((void**)&p_cols, g_cols_hl);
    cudaGetSymbolAddress((void**)&p_hlB, g_hlB);
    cudaGetSymbolAddress((void**)&p_hlC, g_hlC);
    cudaGetSymbolAddress((void**)&p_hlD, g_hlD);

    cudaFuncSetAttribute(conv_mma_kernel,
                         cudaFuncAttributeMaxDynamicSharedMemorySize, CONV_SMEM);

    prep_kernel<<<43776, 256>>>(whh_f, whh_b, bih_f, bhh_f, bih_b, bhh_b,
                                c2_w1, c2_w2, cv_w1, cv_w2);
    build_seq_kernel<<<dim3(512, 8), 256>>>(x2, x1);

    gemm_xg_kernel<<<dim3(256, 16), 256>>>(0, wih_f, wih_b);
    lstm_kernel<<<64, 256>>>(0);
    gemm_xg_kernel<<<dim3(256, 16), 256>>>(1, wih_f, wih_b);
    lstm_kernel<<<64, 256>>>(1);

    // x_site = double_conv(concat([x,x])) via folded weights (A), then c2_w2 (B)
    conv_mma_kernel<<<dim3(256, 2), 256, CONV_SMEM>>>(p_cols, 256, nullptr, 0, WB_A,
                                                      c2_g1, c2_b1, p_hlB, 256, 0);
    conv_mma_kernel<<<dim3(256, 2), 256, CONV_SMEM>>>(p_hlB, 256, nullptr, 0, WB_B,
                                                      c2_g2, c2_b2, p_hlC, 256, 0);
    // x = double_conv(concat([x, x_site]))
    conv_mma_kernel<<<dim3(256, 2), 256, CONV_SMEM>>>(p_cols, 256, p_hlC, 256, WB_C,
                                                      c2_g1, c2_b1, p_hlB, 256, 0);
    conv_mma_kernel<<<dim3(256, 2), 256, CONV_SMEM>>>(p_hlB, 256, nullptr, 0, WB_B,
                                                      c2_g2, c2_b2, p_hlC, 256, 0);
    // final double_conv (cv): 256->128, 128->128 -> d_out (fp32 NCHW)
    conv_mma_kernel<<<dim3(256, 1), 256, CONV_SMEM>>>(p_hlC, 256, nullptr, 0, WB_E,
                                                      cv_g1, cv_b1, p_hlD, 128, 0);
    conv_mma_kernel<<<dim3(256, 1), 256, CONV_SMEM>>>(p_hlD, 128, nullptr, 0, WB_F,
                                                      cv_g2, cv_b2, d_out, 128, 1);
}